// round 3
// baseline (speedup 1.0000x reference)
#include <cuda_runtime.h>
#include <cstdint>

// 12-bit ripple-carry adder over {0,1}-valued float32 arrays.
// A,B: [BATCH, 12] float32, col 11 = LSB (weight 2^(11-i)).
// Out: sums [BATCH,12] at d_out[0..B*12), carry [BATCH] at d_out[B*12..B*13).
//
// Coalescing-first + streaming-cache-hint version:
//  - thread t loads/stores contiguous float4 chunks (512B/warp transactions)
//  - 2 chunks per thread, front-batched loads (MLP 4)
//  - __ldcs/__stcs evict-first hints (620MB stream >> L2, zero reuse)
//  - 3KB smem nibble exchange assembles 12-bit rows; block = 384 thr = 256 rows

__device__ __forceinline__ unsigned f2b(float x) {
    return __float_as_uint(x) != 0u ? 1u : 0u;   // x is exactly 0.0f or 1.0f
}

__device__ __forceinline__ unsigned pack_nib(float4 a, float4 b) {
    unsigned na = (f2b(a.x) << 3) | (f2b(a.y) << 2) | (f2b(a.z) << 1) | f2b(a.w);
    unsigned nb = (f2b(b.x) << 3) | (f2b(b.y) << 2) | (f2b(b.z) << 1) | f2b(b.w);
    return na | (nb << 4);
}

__device__ __forceinline__ unsigned row_sum(const unsigned* nib, int rb) {
    unsigned c0 = nib[rb + 0], c1 = nib[rb + 1], c2 = nib[rb + 2];
    // chunk j holds bit-weights: j=0 -> bits 11..8, j=1 -> 7..4, j=2 -> 3..0
    unsigned av = ((c0 & 0xFu) << 8) | ((c1 & 0xFu) << 4) | (c2 & 0xFu);
    unsigned bv = ((c0 >> 4) << 8)  | (((c1 >> 4) & 0xFu) << 4) | ((c2 >> 4) & 0xFu);
    return av + bv;   // 13-bit result
}

__device__ __forceinline__ float4 nib_to_f4(unsigned on) {
    float4 o;
    o.x = (on & 8u) ? 1.0f : 0.0f;
    o.y = (on & 4u) ? 1.0f : 0.0f;
    o.z = (on & 2u) ? 1.0f : 0.0f;
    o.w = (on & 1u) ? 1.0f : 0.0f;
    return o;
}

__global__ void __launch_bounds__(384) adder12_kernel(
    const float4* __restrict__ A4,
    const float4* __restrict__ B4,
    float4* __restrict__ S4,      // sums, float4[batch*3]
    float* __restrict__ carry,    // [batch]
    int nchunks,                  // batch*3
    int batch)
{
    __shared__ unsigned nib[768]; // per-chunk: a-nibble | (b-nibble << 4)

    const int tid = threadIdx.x;
    const int c0i = blockIdx.x * 768 + tid;        // chunk 0
    const int c1i = c0i + 384;                     // chunk 1
    const bool v0 = (c0i < nchunks);
    const bool v1 = (c1i < nchunks);

    // Front-batched streaming loads (MLP 4)
    float4 a0, b0, a1, b1;
    if (v0) { a0 = __ldcs(&A4[c0i]); b0 = __ldcs(&B4[c0i]); }
    if (v1) { a1 = __ldcs(&A4[c1i]); b1 = __ldcs(&B4[c1i]); }

    nib[tid]       = v0 ? pack_nib(a0, b0) : 0u;
    nib[tid + 384] = v1 ? pack_nib(a1, b1) : 0u;
    __syncthreads();

    // Output chunk 0
    {
        int lrow = tid / 3;
        int part = tid - lrow * 3;
        unsigned s = row_sum(nib, lrow * 3);
        unsigned on = (s >> (8 - 4 * part)) & 0xFu;
        if (v0) __stcs(&S4[c0i], nib_to_f4(on));
    }
    // Output chunk 1
    {
        int k = tid + 384;
        int lrow = k / 3;
        int part = k - lrow * 3;
        unsigned s = row_sum(nib, lrow * 3);
        unsigned on = (s >> (8 - 4 * part)) & 0xFu;
        if (v1) __stcs(&S4[c1i], nib_to_f4(on));
    }

    // Carry-out: threads 0..255 each handle one of the block's 256 rows.
    if (tid < 256) {
        int row = blockIdx.x * 256 + tid;
        if (row < batch) {
            unsigned s = row_sum(nib, tid * 3);
            __stcs(&carry[row], (s >> 12) ? 1.0f : 0.0f);
        }
    }
}

extern "C" void kernel_launch(void* const* d_in, const int* in_sizes, int n_in,
                              void* d_out, int out_size) {
    const float* A = (const float*)d_in[0];
    const float* B = (const float*)d_in[1];
    float* out = (float*)d_out;

    int batch = in_sizes[0] / 12;
    int nchunks = batch * 3;

    float* sums = out;
    float* carry = out + (long)batch * 12;

    int rows_per_block = 256;
    int blocks = (batch + rows_per_block - 1) / rows_per_block;
    adder12_kernel<<<blocks, 384>>>(
        (const float4*)A, (const float4*)B, (float4*)sums, carry, nchunks, batch);
}